// round 1
// baseline (speedup 1.0000x reference)
#include <cuda_runtime.h>

// Problem constants
#define N_BATCH 16
#define C_IN    64
#define K_OUT   64
#define H_IN    130
#define W_IN    130
#define T_DIM   32          // tiles per spatial dim
#define P_TILES 16384       // N * T * T
#define H_OUT   128

// Scratch (device globals: allocation-free rule)
__device__ float g_U[36 * C_IN * K_OUT];        // [e][c][k]
__device__ float g_V[36 * C_IN * P_TILES];      // [e][c][p]   151 MB
__device__ float g_M[36 * K_OUT * P_TILES];     // [e][k][p]   151 MB

// ---------------------------------------------------------------------------
// packed fp32x2 helpers (SASS FFMA2 — double-rate fp32 on sm_103a)
// ---------------------------------------------------------------------------
__device__ __forceinline__ unsigned long long pack2(float x) {
    unsigned long long r;
    asm("mov.b64 %0, {%1, %1};" : "=l"(r) : "f"(x));
    return r;
}
__device__ __forceinline__ void fma2(unsigned long long& d,
                                     unsigned long long a,
                                     unsigned long long b) {
    asm("fma.rn.f32x2 %0, %1, %2, %0;" : "+l"(d) : "l"(a), "l"(b));
}

// ---------------------------------------------------------------------------
// Kernel 1: filter transform  U[k,c] = G w[k,c] G^T   -> g_U[e][c][k]
// ---------------------------------------------------------------------------
__global__ void filter_transform(const float* __restrict__ w) {
    int gid = blockIdx.x * blockDim.x + threadIdx.x;   // 4096 threads
    int k = gid & 63;
    int c = gid >> 6;

    constexpr float G[6][3] = {
        { 0.25f,        0.f,         0.f       },
        {-1.f/6.f,     -1.f/6.f,    -1.f/6.f   },
        {-1.f/6.f,      1.f/6.f,    -1.f/6.f   },
        { 1.f/24.f,     1.f/12.f,    1.f/6.f   },
        { 1.f/24.f,    -1.f/12.f,    1.f/6.f   },
        { 0.f,          0.f,         1.f       }};

    float wv[3][3];
    const float* wp = w + (k * C_IN + c) * 9;
#pragma unroll
    for (int i = 0; i < 3; i++)
#pragma unroll
        for (int j = 0; j < 3; j++) wv[i][j] = wp[i * 3 + j];

    float gw[6][3];
#pragma unroll
    for (int a = 0; a < 6; a++)
#pragma unroll
        for (int j = 0; j < 3; j++)
            gw[a][j] = G[a][0] * wv[0][j] + G[a][1] * wv[1][j] + G[a][2] * wv[2][j];

#pragma unroll
    for (int a = 0; a < 6; a++)
#pragma unroll
        for (int b = 0; b < 6; b++) {
            float u = gw[a][0] * G[b][0] + gw[a][1] * G[b][1] + gw[a][2] * G[b][2];
            g_U[((a * 6 + b) * C_IN + c) * K_OUT + k] = u;
        }
}

// ---------------------------------------------------------------------------
// Kernel 2: input transform  V = B^T d B  -> g_V[e][c][p] (p contiguous)
// ---------------------------------------------------------------------------
__global__ void input_transform(const float* __restrict__ x) {
    int p = blockIdx.x * 32 + threadIdx.x;             // tile index, tx fastest
    int c = blockIdx.y * 4 + threadIdx.y;
    int n = p >> 10;
    int t = (p >> 5) & 31;   // tile row
    int s = p & 31;          // tile col

    const float* base = x + (((size_t)(n * C_IN + c) * H_IN) + t * 4) * W_IN + s * 4;

    float d[6][6];
#pragma unroll
    for (int i = 0; i < 6; i++)
#pragma unroll
        for (int j = 0; j < 6; j++) d[i][j] = base[i * W_IN + j];

    constexpr float BT[6][6] = {
        {4.f, 0.f, -5.f,  0.f, 1.f, 0.f},
        {0.f,-4.f, -4.f,  1.f, 1.f, 0.f},
        {0.f, 4.f, -4.f, -1.f, 1.f, 0.f},
        {0.f,-2.f, -1.f,  2.f, 1.f, 0.f},
        {0.f, 2.f, -1.f, -2.f, 1.f, 0.f},
        {0.f, 4.f,  0.f, -5.f, 0.f, 1.f}};

    float t1[6][6];
#pragma unroll
    for (int a = 0; a < 6; a++)
#pragma unroll
        for (int j = 0; j < 6; j++) {
            float acc = 0.f;
#pragma unroll
            for (int i = 0; i < 6; i++) acc += BT[a][i] * d[i][j];   // zeros fold
            t1[a][j] = acc;
        }

#pragma unroll
    for (int a = 0; a < 6; a++)
#pragma unroll
        for (int b = 0; b < 6; b++) {
            float acc = 0.f;
#pragma unroll
            for (int j = 0; j < 6; j++) acc += t1[a][j] * BT[b][j];
            g_V[((size_t)(a * 6 + b) * C_IN + c) * P_TILES + p] = acc;
        }
}

// ---------------------------------------------------------------------------
// Kernel 3: batched GEMM per tile-domain element e:
//   M[e][k][p] = sum_c U[e][c][k] * V[e][c][p]
// CTA tile: 64 k x 128 p, c chunks of 32. Thread: 4k x 8p via f32x2.
// ---------------------------------------------------------------------------
__global__ __launch_bounds__(256) void winograd_gemm() {
    __shared__ float Us[32][64];     // [c][k]
    __shared__ float Vs[32][128];    // [c][p]

    const int e  = blockIdx.y;
    const int p0 = blockIdx.x * 128;
    const int tx = threadIdx.x;      // p dim, 0..15
    const int ty = threadIdx.y;      // k dim, 0..15
    const int tid = ty * 16 + tx;

    unsigned long long acc[4][4];
#pragma unroll
    for (int i = 0; i < 4; i++)
#pragma unroll
        for (int j = 0; j < 4; j++) acc[i][j] = 0ull;   // {0.f,0.f}

    const float* Ue = g_U + (size_t)e * (C_IN * K_OUT);
    const float* Ve = g_V + (size_t)e * C_IN * P_TILES + p0;

    for (int cc = 0; cc < C_IN; cc += 32) {
        // load U chunk: 32x64 floats, 8 per thread
        {
            int r = tid >> 4;              // 0..15
            int col = (tid & 15) * 4;
            *(float4*)&Us[r][col]      = *(const float4*)&Ue[(cc + r) * K_OUT + col];
            *(float4*)&Us[r + 16][col] = *(const float4*)&Ue[(cc + r + 16) * K_OUT + col];
        }
        // load V chunk: 32x128 floats, 16 per thread
        {
            int r = tid >> 5;              // 0..7
            int col = (tid & 31) * 4;
#pragma unroll
            for (int q = 0; q < 4; q++)
                *(float4*)&Vs[r + q * 8][col] =
                    *(const float4*)&Ve[(size_t)(cc + r + q * 8) * P_TILES + col];
        }
        __syncthreads();

#pragma unroll
        for (int c = 0; c < 32; c++) {
            float4 av = *(const float4*)&Us[c][ty * 4];          // broadcast LDS.128
            unsigned long long a0 = pack2(av.x), a1 = pack2(av.y);
            unsigned long long a2 = pack2(av.z), a3 = pack2(av.w);
            ulonglong2 b01 = *(const ulonglong2*)&Vs[c][tx * 8];
            ulonglong2 b23 = *(const ulonglong2*)&Vs[c][tx * 8 + 4];

            fma2(acc[0][0], a0, b01.x); fma2(acc[0][1], a0, b01.y);
            fma2(acc[0][2], a0, b23.x); fma2(acc[0][3], a0, b23.y);
            fma2(acc[1][0], a1, b01.x); fma2(acc[1][1], a1, b01.y);
            fma2(acc[1][2], a1, b23.x); fma2(acc[1][3], a1, b23.y);
            fma2(acc[2][0], a2, b01.x); fma2(acc[2][1], a2, b01.y);
            fma2(acc[2][2], a2, b23.x); fma2(acc[2][3], a2, b23.y);
            fma2(acc[3][0], a3, b01.x); fma2(acc[3][1], a3, b01.y);
            fma2(acc[3][2], a3, b23.x); fma2(acc[3][3], a3, b23.y);
        }
        __syncthreads();
    }

    float* Me = g_M + (size_t)e * K_OUT * P_TILES + p0;
#pragma unroll
    for (int i = 0; i < 4; i++) {
        float* row = Me + (size_t)(ty * 4 + i) * P_TILES + tx * 8;
        *(ulonglong2*)row       = make_ulonglong2(acc[i][0], acc[i][1]);
        *(ulonglong2*)(row + 4) = make_ulonglong2(acc[i][2], acc[i][3]);
    }
}

// ---------------------------------------------------------------------------
// Kernel 4: output transform  Y = A^T M A  per (p,k), write NK 128x128
// ---------------------------------------------------------------------------
__global__ void output_transform(float* __restrict__ out) {
    int p = blockIdx.x * 32 + threadIdx.x;   // p fastest -> coalesced reads & writes
    int k = blockIdx.y * 8 + threadIdx.y;

    float m[6][6];
#pragma unroll
    for (int a = 0; a < 6; a++)
#pragma unroll
        for (int b = 0; b < 6; b++)
            m[a][b] = g_M[((size_t)(a * 6 + b) * K_OUT + k) * P_TILES + p];

    constexpr float AT[4][6] = {
        {1.f, 1.f,  1.f, 1.f,  1.f, 0.f},
        {0.f, 1.f, -1.f, 2.f, -2.f, 0.f},
        {0.f, 1.f,  1.f, 4.f,  4.f, 0.f},
        {0.f, 1.f, -1.f, 8.f, -8.f, 1.f}};

    float t2[4][6];
#pragma unroll
    for (int xr = 0; xr < 4; xr++)
#pragma unroll
        for (int j = 0; j < 6; j++) {
            float acc = 0.f;
#pragma unroll
            for (int i = 0; i < 6; i++) acc += AT[xr][i] * m[i][j];
            t2[xr][j] = acc;
        }

    int n = p >> 10;
    int t = (p >> 5) & 31;
    int s = p & 31;
    float* ob = out + (((size_t)(n * K_OUT + k) * H_OUT) + t * 4) * H_OUT + s * 4;

#pragma unroll
    for (int xr = 0; xr < 4; xr++) {
        float4 y;
        float* yy = &y.x;
#pragma unroll
        for (int b = 0; b < 4; b++) {
            float acc = 0.f;
#pragma unroll
            for (int j = 0; j < 6; j++) acc += t2[xr][j] * AT[b][j];
            yy[b] = acc;
        }
        *(float4*)&ob[xr * H_OUT] = y;
    }
}

// ---------------------------------------------------------------------------
extern "C" void kernel_launch(void* const* d_in, const int* in_sizes, int n_in,
                              void* d_out, int out_size) {
    const float* x = (const float*)d_in[0];   // (16,64,130,130)
    const float* w = (const float*)d_in[1];   // (64,64,3,3)
    float* out = (float*)d_out;               // (16,64,128,128)

    filter_transform<<<16, 256>>>(w);
    input_transform<<<dim3(P_TILES / 32, C_IN / 4), dim3(32, 4)>>>(x);
    winograd_gemm<<<dim3(P_TILES / 128, 36), dim3(16, 16)>>>();
    output_transform<<<dim3(P_TILES / 32, K_OUT / 8), dim3(32, 8)>>>(out);
}

// round 3
// speedup vs baseline: 1.5432x; 1.5432x over previous
#include <cuda_runtime.h>
#include <cuda_bf16.h>
#include <cstdint>

#define C_IN    64
#define K_OUT   64
#define H_IN    130
#define W_IN    130
#define P_TILES 16384
#define H_OUT   128

// Scratch (device globals: allocation-free rule)
__device__ float g_U[36 * K_OUT * C_IN];            // [e][k][c]
__device__ float g_V[(size_t)36 * P_TILES * C_IN];  // [e][p][c]   151 MB
__device__ float g_M[(size_t)36 * K_OUT * P_TILES]; // [e][k][p]   151 MB

__device__ __forceinline__ uint32_t smem_u32(const void* p) {
    uint32_t a;
    asm("{ .reg .u64 t; cvta.to.shared.u64 t, %1; cvt.u32.u64 %0, t; }"
        : "=r"(a) : "l"(p));
    return a;
}

#define LDSM4(r, a)                                                          \
    asm volatile("ldmatrix.sync.aligned.m8n8.x4.shared.b16 {%0,%1,%2,%3}, [%4];" \
                 : "=r"((r)[0]), "=r"((r)[1]), "=r"((r)[2]), "=r"((r)[3])    \
                 : "r"(a))

#define MMA_BF16(c, a, b0, b1)                                               \
    asm volatile("mma.sync.aligned.m16n8k16.row.col.f32.bf16.bf16.f32 "      \
                 "{%0,%1,%2,%3},{%4,%5,%6,%7},{%8,%9},{%0,%1,%2,%3};"        \
                 : "+f"((c)[0]), "+f"((c)[1]), "+f"((c)[2]), "+f"((c)[3])    \
                 : "r"((a)[0]), "r"((a)[1]), "r"((a)[2]), "r"((a)[3]),       \
                   "r"(b0), "r"(b1))

// split 8 consecutive fp32 into bf16 hi / lo 16B chunks
__device__ __forceinline__ void split8(const float* __restrict__ src,
                                       uint4& H, uint4& L) {
    float x[8];
    *(float4*)(x)     = *(const float4*)(src);
    *(float4*)(x + 4) = *(const float4*)(src + 4);
    unsigned short hs[8], ls[8];
#pragma unroll
    for (int j = 0; j < 8; j++) {
        __nv_bfloat16 h = __float2bfloat16_rn(x[j]);
        float hf = __bfloat162float(h);
        __nv_bfloat16 l = __float2bfloat16_rn(x[j] - hf);
        hs[j] = *(unsigned short*)&h;
        ls[j] = *(unsigned short*)&l;
    }
    H = *(uint4*)hs;
    L = *(uint4*)ls;
}

// ---------------------------------------------------------------------------
// Kernel 1: filter transform -> g_U[e][k][c]
// ---------------------------------------------------------------------------
__global__ void filter_transform(const float* __restrict__ w) {
    int gid = blockIdx.x * blockDim.x + threadIdx.x;
    int c = gid & 63;
    int k = gid >> 6;

    constexpr float G[6][3] = {
        { 0.25f,     0.f,       0.f     },
        {-1.f/6.f,  -1.f/6.f,  -1.f/6.f },
        {-1.f/6.f,   1.f/6.f,  -1.f/6.f },
        { 1.f/24.f,  1.f/12.f,  1.f/6.f },
        { 1.f/24.f, -1.f/12.f,  1.f/6.f },
        { 0.f,       0.f,       1.f     }};

    float wv[3][3];
    const float* wp = w + (k * C_IN + c) * 9;
#pragma unroll
    for (int i = 0; i < 3; i++)
#pragma unroll
        for (int j = 0; j < 3; j++) wv[i][j] = wp[i * 3 + j];

    float gw[6][3];
#pragma unroll
    for (int a = 0; a < 6; a++)
#pragma unroll
        for (int j = 0; j < 3; j++)
            gw[a][j] = G[a][0] * wv[0][j] + G[a][1] * wv[1][j] + G[a][2] * wv[2][j];

#pragma unroll
    for (int a = 0; a < 6; a++)
#pragma unroll
        for (int b = 0; b < 6; b++) {
            float u = gw[a][0] * G[b][0] + gw[a][1] * G[b][1] + gw[a][2] * G[b][2];
            g_U[((a * 6 + b) * K_OUT + k) * C_IN + c] = u;
        }
}

// ---------------------------------------------------------------------------
// Kernel 2: input transform -> g_V[e][p][c] (fp32, c contiguous)
// ---------------------------------------------------------------------------
__global__ __launch_bounds__(256) void input_transform2(const float* __restrict__ x) {
    __shared__ float Vs[36][16][17];   // [e][c_l][s_l]

    int tid = threadIdx.x;
    int nt = blockIdx.x;               // 0..511
    int n = nt >> 5, t = nt & 31;
    int sh = blockIdx.y;               // 0..1
    int ch = blockIdx.z;               // 0..3

    int s_l = tid & 15, c_l = tid >> 4;
    int c = ch * 16 + c_l;
    int s = sh * 16 + s_l;

    const float* base = x + ((size_t)(n * C_IN + c) * H_IN + t * 4) * W_IN + s * 4;

    float d[6][6];
#pragma unroll
    for (int i = 0; i < 6; i++)
#pragma unroll
        for (int j = 0; j < 6; j++) d[i][j] = base[i * W_IN + j];

    constexpr float BT[6][6] = {
        {4.f, 0.f, -5.f,  0.f, 1.f, 0.f},
        {0.f,-4.f, -4.f,  1.f, 1.f, 0.f},
        {0.f, 4.f, -4.f, -1.f, 1.f, 0.f},
        {0.f,-2.f, -1.f,  2.f, 1.f, 0.f},
        {0.f, 2.f, -1.f, -2.f, 1.f, 0.f},
        {0.f, 4.f,  0.f, -5.f, 0.f, 1.f}};

    float t1[6][6];
#pragma unroll
    for (int a = 0; a < 6; a++)
#pragma unroll
        for (int j = 0; j < 6; j++) {
            float acc = 0.f;
#pragma unroll
            for (int i = 0; i < 6; i++) acc += BT[a][i] * d[i][j];
            t1[a][j] = acc;
        }
#pragma unroll
    for (int a = 0; a < 6; a++)
#pragma unroll
        for (int b = 0; b < 6; b++) {
            float acc = 0.f;
#pragma unroll
            for (int j = 0; j < 6; j++) acc += t1[a][j] * BT[b][j];
            Vs[a * 6 + b][c_l][s_l] = acc;
        }
    __syncthreads();

    int c_w = tid & 15, s_w = tid >> 4;
    size_t pbase = (size_t)(n * 1024 + t * 32 + sh * 16) + s_w;
    float* dst = g_V + pbase * C_IN + ch * 16 + c_w;
#pragma unroll
    for (int e = 0; e < 36; e++)
        dst[(size_t)e * P_TILES * C_IN] = Vs[e][c_w][s_w];
}

// ---------------------------------------------------------------------------
// Kernel 3: bf16 3-split HMMA GEMM.
//   per CTA: one e, 128p x 64k, full c=64.
//   M[e][k][p] = sum_c U[e][k][c] * V[e][p][c]
// smem: Ahi(16K) Alo(16K) Bhi(8K) Blo(8K) Ms(64x132 f32 = 33K)
// ---------------------------------------------------------------------------
#define SM_AHI 0u
#define SM_ALO 16384u
#define SM_BHI 32768u
#define SM_BLO 40960u
#define SM_MS  49152u
#define GEMM_SMEM (49152u + 64u * 132u * 4u)   // 82944 B

__global__ __launch_bounds__(256, 2) void winograd_gemm_mma() {
    extern __shared__ __align__(128) char smem[];
    const uint32_t sb = smem_u32(smem);
    const int tid = threadIdx.x;
    const int lane = tid & 31;
    const int wid = tid >> 5;
    const int e = blockIdx.y;
    const size_t p0 = (size_t)blockIdx.x * 128;

    const float* Ag = g_V + ((size_t)e * P_TILES + p0) * C_IN;  // [128][64]
    const float* Bg = g_U + (size_t)e * K_OUT * C_IN;           // [64][64]

    // ---- load B (U) 64x64: 512 chunks of 8c, 2 per thread ----
#pragma unroll
    for (int i = 0; i < 2; i++) {
        int chk = tid + i * 256;
        int r = chk >> 3, cc = chk & 7;
        uint4 H, L;
        split8(Bg + r * 64 + cc * 8, H, L);
        uint32_t off = (uint32_t)(r * 128) + (((uint32_t)(cc ^ (r & 7))) << 4);
        *(uint4*)(smem + SM_BHI + off) = H;
        *(uint4*)(smem + SM_BLO + off) = L;
    }
    // ---- load A (V) 128x64: 1024 chunks, 4 per thread ----
#pragma unroll
    for (int i = 0; i < 4; i++) {
        int chk = tid + i * 256;
        int r = chk >> 3, cc = chk & 7;
        uint4 H, L;
        split8(Ag + (size_t)r * 64 + cc * 8, H, L);
        uint32_t off = (uint32_t)(r * 128) + (((uint32_t)(cc ^ (r & 7))) << 4);
        *(uint4*)(smem + SM_AHI + off) = H;
        *(uint4*)(smem + SM_ALO + off) = L;
    }
    __syncthreads();

    const int wp = wid >> 1;   // 0..3 : p block of 32
    const int wk = wid & 1;    // 0..1 : k block of 32

    float acc[2][4][4];
#pragma unroll
    for (int mi = 0; mi < 2; mi++)
#pragma unroll
        for (int ni = 0; ni < 4; ni++)
#pragma unroll
            for (int q = 0; q < 4; q++) acc[mi][ni][q] = 0.f;

#pragma unroll
    for (int ks = 0; ks < 4; ks++) {
        uint32_t ahi[2][4], alo[2][4], bhi[2][4], blo[2][4];
        int chunk = ks * 2 + (lane >> 4);
#pragma unroll
        for (int mi = 0; mi < 2; mi++) {
            int row = wp * 32 + mi * 16 + (lane & 15);
            uint32_t a = sb + (uint32_t)(row * 128) + (((uint32_t)(chunk ^ (row & 7))) << 4);
            LDSM4(ahi[mi], a + SM_AHI);
            LDSM4(alo[mi], a + SM_ALO);
        }
#pragma unroll
        for (int n2 = 0; n2 < 2; n2++) {
            int row = wk * 32 + n2 * 16 + (lane & 15);
            uint32_t a = sb + (uint32_t)(row * 128) + (((uint32_t)(chunk ^ (row & 7))) << 4);
            LDSM4(bhi[n2], a + SM_BHI);
            LDSM4(blo[n2], a + SM_BLO);
        }
#pragma unroll
        for (int mi = 0; mi < 2; mi++)
#pragma unroll
            for (int ni = 0; ni < 4; ni++) {
                int n2 = ni >> 1, sel = ni & 1;
                uint32_t b0h = bhi[n2][sel],     b1h = bhi[n2][sel + 2];
                uint32_t b0l = blo[n2][sel],     b1l = blo[n2][sel + 2];
                MMA_BF16(acc[mi][ni], ahi[mi], b0h, b1h);   // hi*hi
                MMA_BF16(acc[mi][ni], ahi[mi], b0l, b1l);   // hi*lo
                MMA_BF16(acc[mi][ni], alo[mi], b0h, b1h);   // lo*hi
            }
    }

    // ---- epilogue: acc -> Ms[k][p] (stride 132, conflict-free) ----
    float* Ms = (float*)(smem + SM_MS);
#pragma unroll
    for (int mi = 0; mi < 2; mi++)
#pragma unroll
        for (int ni = 0; ni < 4; ni++) {
            int prow = wp * 32 + mi * 16 + (lane >> 2);
            int kcol = wk * 32 + ni * 8 + (lane & 3) * 2;
            Ms[kcol * 132 + prow]           = acc[mi][ni][0];
            Ms[(kcol + 1) * 132 + prow]     = acc[mi][ni][1];
            Ms[kcol * 132 + prow + 8]       = acc[mi][ni][2];
            Ms[(kcol + 1) * 132 + prow + 8] = acc[mi][ni][3];
        }
    __syncthreads();

    // ---- coalesced store: g_M[e][k][p0..p0+128) ----
    float* Me = g_M + (size_t)e * K_OUT * P_TILES + p0;
#pragma unroll
    for (int it = 0; it < 8; it++) {
        int k = wid * 8 + it;
        float4 v = *(float4*)&Ms[k * 132 + lane * 4];
        *(float4*)&Me[(size_t)k * P_TILES + lane * 4] = v;
    }
}

// ---------------------------------------------------------------------------
// Kernel 4: output transform  Y = A^T M A
// ---------------------------------------------------------------------------
__global__ void output_transform(float* __restrict__ out) {
    int p = blockIdx.x * 32 + threadIdx.x;
    int k = blockIdx.y * 8 + threadIdx.y;

    float m[6][6];
#pragma unroll
    for (int a = 0; a < 6; a++)
#pragma unroll
        for (int b = 0; b < 6; b++)
            m[a][b] = g_M[((size_t)(a * 6 + b) * K_OUT + k) * P_TILES + p];

    constexpr float AT[4][6] = {
        {1.f, 1.f,  1.f, 1.f,  1.f, 0.f},
        {0.f, 1.f, -1.f, 2.f, -2.f, 0.f},
        {0.f, 1.f,  1.f, 4.f,  4.f, 0.f},
        {0.f, 1.f, -1.f, 8.f, -8.f, 1.f}};

    float t2[4][6];
#pragma unroll
    for (int xr = 0; xr < 4; xr++)
#pragma unroll
        for (int j = 0; j < 6; j++) {
            float acc = 0.f;
#pragma unroll
            for (int i = 0; i < 6; i++) acc += AT[xr][i] * m[i][j];
            t2[xr][j] = acc;
        }

    int n = p >> 10;
    int t = (p >> 5) & 31;
    int s = p & 31;
    float* ob = out + (((size_t)(n * K_OUT + k) * H_OUT) + t * 4) * H_OUT + s * 4;

#pragma unroll
    for (int xr = 0; xr < 4; xr++) {
        float4 y;
        float* yy = &y.x;
#pragma unroll
        for (int b = 0; b < 4; b++) {
            float acc = 0.f;
#pragma unroll
            for (int j = 0; j < 6; j++) acc += t2[xr][j] * AT[b][j];
            yy[b] = acc;
        }
        *(float4*)&ob[xr * H_OUT] = y;
    }
}

// ---------------------------------------------------------------------------
extern "C" void kernel_launch(void* const* d_in, const int* in_sizes, int n_in,
                              void* d_out, int out_size) {
    const float* x = (const float*)d_in[0];   // (16,64,130,130)
    const float* w = (const float*)d_in[1];   // (64,64,3,3)
    float* out = (float*)d_out;               // (16,64,128,128)

    cudaFuncSetAttribute(winograd_gemm_mma,
                         cudaFuncAttributeMaxDynamicSharedMemorySize, GEMM_SMEM);

    filter_transform<<<16, 256>>>(w);
    input_transform2<<<dim3(512, 2, 4), 256>>>(x);
    winograd_gemm_mma<<<dim3(P_TILES / 128, 36), 256, GEMM_SMEM>>>();
    output_transform<<<dim3(P_TILES / 32, K_OUT / 8), dim3(32, 8)>>>(out);
}